// round 5
// baseline (speedup 1.0000x reference)
#include <cuda_runtime.h>
#include <cstdint>

// NoiseLinear: out[b,o] = sum_i x[b,i]*w[o,i]*(1 + 0.1*eps[b,o,i]) + bias[o]
// eps = jax.random.normal(key(seed), (B,OUT,IN)) — partitionable threefry
// (bit-model verified; rel_err ~6e-7 baseline).
// R5: narrow body (float2 loads, 4 chains/iter instead of 8) to spread MUFU
// bursts and shrink the live-register scheduling window; 0.1 folded into the
// erfinv polynomial so m = fma(p,u,1) gives (1+0.1*eps) with no extra FMUL.

#define B_DIM  64
#define IN_DIM 1024
#define OUT_DIM 4096

// Full 20-round threefry2x32 with key (0, seed); returns o0 ^ o1.
// c1k = counter + ks1 (ks1 pre-folded by caller).
__device__ __forceinline__ uint32_t tf2x32_bits(uint32_t ks1, uint32_t ks2,
                                                uint32_t c1k) {
    uint32_t x0, x1 = c1k;
    x0 = x1;                                    // round 1 add (x0_init = 0)
    x1 = __funnelshift_l(x1, x1, 13); x1 ^= x0;
#define TF_R(r) { x0 += x1; x1 = __funnelshift_l(x1, x1, (r)); x1 ^= x0; }
    TF_R(15) TF_R(26) TF_R(6)
    x0 += ks1;      x1 += ks2 + 1u;
    TF_R(17) TF_R(29) TF_R(16) TF_R(24)
    x0 += ks2;      x1 += 2u;                   // + ks0(=0) + 2
    TF_R(13) TF_R(15) TF_R(26) TF_R(6)
    /* x0 += ks0 */ x1 += ks1 + 3u;
    TF_R(17) TF_R(29) TF_R(16) TF_R(24)
    x0 += ks1;      x1 += ks2 + 4u;
    TF_R(13) TF_R(15) TF_R(26) TF_R(6)
    x0 += ks2;      x1 += 5u;                   // + ks0(=0) + 5
#undef TF_R
    return x0 ^ x1;
}

// bits -> m = 1 + 0.1*sqrt(2)*erfinv(u); 0.1*sqrt(2) folded into both
// polynomial branches. Central branch in s = log2(1-u^2) + 2.5/ln2 domain.
__device__ __forceinline__ float bits_to_m(uint32_t bits) {
    float v = __uint_as_float((bits >> 9) + 0x3f800000u);   // [1,2)
    float u = __fmaf_rn(v, 2.0f, -3.0f);                    // ~[-1,1)
    u = fmaxf(u, -0.99999994f);                             // keep 1-u^2 > 0
    float t = __fmaf_rn(u, -u, 1.0f);                       // (0,1]
    float L = __log2f(t);                                   // <= 0
    float s = __fadd_rn(L, 3.6067376f);                     // L + 2.5/ln2
    float p;
    p = 2.1176117e-10f;
    p = __fmaf_rn(p, s, -3.7320261e-09f);
    p = __fmaf_rn(p, s, -5.5262276e-08f);
    p = __fmaf_rn(p, s, 9.9370005e-08f);
    p = __fmaf_rn(p, s, 7.1355326e-06f);
    p = __fmaf_rn(p, s, 5.9044926e-05f);
    p = __fmaf_rn(p, s, -2.8386012e-04f);
    p = __fmaf_rn(p, s, -2.4177344e-02f);
    p = __fmaf_rn(p, s, 2.1233136e-01f);
    // rare tail (|u| >= 0.99663, per-lane p=0.34%, warp-any ~10%)
    if (__any_sync(0xFFFFFFFFu, L <= -7.2134752f)) {
        float w  = __fmul_rn(L, -0.69314718f);
        float wq = __fsqrt_rn(w) - 3.0f;
        float q;
        q = -2.8314768e-05f;
        q = __fmaf_rn(q, wq, 1.4276563e-05f);
        q = __fmaf_rn(q, wq, 1.9082642e-04f);
        q = __fmaf_rn(q, wq, -5.1950162e-04f);
        q = __fmaf_rn(q, wq, 8.1168864e-04f);
        q = __fmaf_rn(q, wq, -1.0779783e-03f);
        q = __fmaf_rn(q, wq, 1.3348632e-03f);
        q = __fmaf_rn(q, wq, 1.4165810e-01f);
        q = __fmaf_rn(q, wq, 4.0064343e-01f);
        p = (L <= -7.2134752f) ? q : p;
    }
    return __fmaf_rn(p, u, 1.0f);               // 1 + 0.1*eps
}

// One warp per (b-pair, o). b-pair = (bp, bp+32). Lanes stride IN=1024 with
// float2 loads: 16 iterations, 2 elements x 2 rows = 4 threefry chains/iter.
__global__ void __launch_bounds__(256, 4)
noise_linear_kernel(const float* __restrict__ x, const float* __restrict__ w,
                    const float* __restrict__ bias, const int* __restrict__ seedp,
                    float* __restrict__ out) {
    const uint32_t ks1 = (uint32_t)seedp[0];
    const uint32_t ks2 = ks1 ^ 0x1BD11BDAu;

    const int gw   = blockIdx.x * (blockDim.x >> 5) + (threadIdx.x >> 5);
    const int lane = threadIdx.x & 31;
    const int o  = gw & (OUT_DIM - 1);
    const int bp = gw >> 12;                 // 0..31
    const int b0 = bp, b1 = bp + 32;

    const float2* __restrict__ wrow  = (const float2*)(w + (size_t)o  * IN_DIM);
    const float2* __restrict__ x0row = (const float2*)(x + (size_t)b0 * IN_DIM);
    const float2* __restrict__ x1row = (const float2*)(x + (size_t)b1 * IN_DIM);

    // counter base + ks1 pre-folded
    const uint32_t bk0 = (uint32_t)b0 * (OUT_DIM * IN_DIM)
                       + (uint32_t)o * IN_DIM + ks1;
    const uint32_t bk1 = bk0 + 32u * (OUT_DIM * IN_DIM);

    float acc0 = 0.f, acc1 = 0.f;            // sum of t*(1 + 0.1*eps)

#pragma unroll 1
    for (int ii = 0; ii < IN_DIM / 64; ++ii) {      // 16 iterations
        const int vec = ii * 32 + lane;             // float2 index in the row
        const float2 w2 = __ldg(wrow  + vec);
        const float2 a2 = __ldg(x0row + vec);
        const float2 b2 = __ldg(x1row + vec);
        const uint32_t c0 = bk0 + (uint32_t)vec * 2u;
        const uint32_t c1 = bk1 + (uint32_t)vec * 2u;

        // element 0
        {
            const float t0 = __fmul_rn(w2.x, a2.x);
            const float t1 = __fmul_rn(w2.x, b2.x);
            const float m0 = bits_to_m(tf2x32_bits(ks1, ks2, c0));
            const float m1 = bits_to_m(tf2x32_bits(ks1, ks2, c1));
            acc0 = __fmaf_rn(m0, t0, acc0);
            acc1 = __fmaf_rn(m1, t1, acc1);
        }
        // element 1
        {
            const float t0 = __fmul_rn(w2.y, a2.y);
            const float t1 = __fmul_rn(w2.y, b2.y);
            const float m0 = bits_to_m(tf2x32_bits(ks1, ks2, c0 + 1u));
            const float m1 = bits_to_m(tf2x32_bits(ks1, ks2, c1 + 1u));
            acc0 = __fmaf_rn(m0, t0, acc0);
            acc1 = __fmaf_rn(m1, t1, acc1);
        }
    }

    // warp butterfly reduce (2 accumulators)
#pragma unroll
    for (int off = 16; off > 0; off >>= 1) {
        acc0 += __shfl_xor_sync(0xFFFFFFFFu, acc0, off);
        acc1 += __shfl_xor_sync(0xFFFFFFFFu, acc1, off);
    }

    if (lane == 0) {
        const float bz = __ldg(bias + o);
        out[(size_t)b0 * OUT_DIM + o] = acc0 + bz;
        out[(size_t)b1 * OUT_DIM + o] = acc1 + bz;
    }
}

extern "C" void kernel_launch(void* const* d_in, const int* in_sizes, int n_in,
                              void* d_out, int out_size) {
    const float* x    = (const float*)d_in[0];
    const float* w    = (const float*)d_in[1];
    const float* bias = (const float*)d_in[2];
    const int*   seed = (const int*)d_in[3];
    float* out = (float*)d_out;

    // 32 b-pairs * 4096 outputs = 131072 warps; 8 warps/block -> 16384 blocks
    noise_linear_kernel<<<16384, 256>>>(x, w, bias, seed, out);
}

// round 6
// speedup vs baseline: 1.0378x; 1.0378x over previous
#include <cuda_runtime.h>
#include <cstdint>

// NoiseLinear: out[b,o] = sum_i x[b,i]*w[o,i]*(1 + 0.1*eps[b,o,i]) + bias[o]
// eps = jax.random.normal(key(seed), (B,OUT,IN)) — partitionable threefry
// (bit-model verified, rel_err ~6e-7).
// R6: R4 structure widened to 4 batch rows per warp (w-load amortized 4x,
// 16 independent threefry chains per body for ILP) + R5's validated m-fold
// (0.1*sqrt(2) folded into erfinv coeffs; m = fma(p,u,1)).

#define B_DIM  64
#define IN_DIM 1024
#define OUT_DIM 4096

// Full 20-round threefry2x32, key (0, seed); returns o0 ^ o1.
// c1k = counter + ks1 (ks1 pre-folded by caller).
__device__ __forceinline__ uint32_t tf2x32_bits(uint32_t ks1, uint32_t ks2,
                                                uint32_t c1k) {
    uint32_t x0, x1 = c1k;
    x0 = x1;                                    // round 1 add (x0_init = 0)
    x1 = __funnelshift_l(x1, x1, 13); x1 ^= x0;
#define TF_R(r) { x0 += x1; x1 = __funnelshift_l(x1, x1, (r)); x1 ^= x0; }
    TF_R(15) TF_R(26) TF_R(6)
    x0 += ks1;      x1 += ks2 + 1u;
    TF_R(17) TF_R(29) TF_R(16) TF_R(24)
    x0 += ks2;      x1 += 2u;                   // + ks0(=0) + 2
    TF_R(13) TF_R(15) TF_R(26) TF_R(6)
    /* x0 += ks0 */ x1 += ks1 + 3u;
    TF_R(17) TF_R(29) TF_R(16) TF_R(24)
    x0 += ks1;      x1 += ks2 + 4u;
    TF_R(13) TF_R(15) TF_R(26) TF_R(6)
    x0 += ks2;      x1 += 5u;                   // + ks0(=0) + 5
#undef TF_R
    return x0 ^ x1;
}

// bits -> m = 1 + 0.1*sqrt(2)*erfinv(u); 0.1*sqrt(2) folded into both
// polynomial branches. Central branch in s = log2(1-u^2) + 2.5/ln2 domain.
__device__ __forceinline__ float bits_to_m(uint32_t bits) {
    float v = __uint_as_float((bits >> 9) + 0x3f800000u);   // [1,2)
    float u = __fmaf_rn(v, 2.0f, -3.0f);                    // ~[-1,1)
    u = fmaxf(u, -0.99999994f);                             // keep 1-u^2 > 0
    float t = __fmaf_rn(u, -u, 1.0f);                       // (0,1]
    float L = __log2f(t);                                   // <= 0
    float s = __fadd_rn(L, 3.6067376f);                     // L + 2.5/ln2
    float p;
    p = 2.1176117e-10f;
    p = __fmaf_rn(p, s, -3.7320261e-09f);
    p = __fmaf_rn(p, s, -5.5262276e-08f);
    p = __fmaf_rn(p, s, 9.9370005e-08f);
    p = __fmaf_rn(p, s, 7.1355326e-06f);
    p = __fmaf_rn(p, s, 5.9044926e-05f);
    p = __fmaf_rn(p, s, -2.8386012e-04f);
    p = __fmaf_rn(p, s, -2.4177344e-02f);
    p = __fmaf_rn(p, s, 2.1233136e-01f);
    // rare tail (|u| >= 0.99663; per-lane p=0.34%, warp-any ~10%)
    if (__any_sync(0xFFFFFFFFu, L <= -7.2134752f)) {
        float w  = __fmul_rn(L, -0.69314718f);
        float wq = __fsqrt_rn(w) - 3.0f;
        float q;
        q = -2.8314768e-05f;
        q = __fmaf_rn(q, wq, 1.4276563e-05f);
        q = __fmaf_rn(q, wq, 1.9082642e-04f);
        q = __fmaf_rn(q, wq, -5.1950162e-04f);
        q = __fmaf_rn(q, wq, 8.1168864e-04f);
        q = __fmaf_rn(q, wq, -1.0779783e-03f);
        q = __fmaf_rn(q, wq, 1.3348632e-03f);
        q = __fmaf_rn(q, wq, 1.4165810e-01f);
        q = __fmaf_rn(q, wq, 4.0064343e-01f);
        p = (L <= -7.2134752f) ? q : p;
    }
    return __fmaf_rn(p, u, 1.0f);               // 1 + 0.1*eps
}

// One warp per (b-quad, o). b-quad = bp, bp+16, bp+32, bp+48; bp in [0,16).
// Lanes stride IN=1024 with float4 loads; 16 threefry chains per loop body.
__global__ void __launch_bounds__(256, 4)
noise_linear_kernel(const float* __restrict__ x, const float* __restrict__ w,
                    const float* __restrict__ bias, const int* __restrict__ seedp,
                    float* __restrict__ out) {
    const uint32_t ks1 = (uint32_t)seedp[0];
    const uint32_t ks2 = ks1 ^ 0x1BD11BDAu;

    const int gw   = blockIdx.x * (blockDim.x >> 5) + (threadIdx.x >> 5);
    const int lane = threadIdx.x & 31;
    const int o  = gw & (OUT_DIM - 1);
    const int bp = gw >> 12;                 // 0..15

    const float4* __restrict__ wrow  = (const float4*)(w + (size_t)o * IN_DIM);
    const float4* __restrict__ x0row = (const float4*)(x + (size_t)(bp     ) * IN_DIM);
    const float4* __restrict__ x1row = (const float4*)(x + (size_t)(bp + 16) * IN_DIM);
    const float4* __restrict__ x2row = (const float4*)(x + (size_t)(bp + 32) * IN_DIM);
    const float4* __restrict__ x3row = (const float4*)(x + (size_t)(bp + 48) * IN_DIM);

    // counter base + ks1 pre-folded; row stride in flat index = 16*OUT*IN = 2^26
    const uint32_t bk0 = (uint32_t)bp * (OUT_DIM * IN_DIM)
                       + (uint32_t)o * IN_DIM + ks1;
    const uint32_t RS = 16u * OUT_DIM * IN_DIM;

    float acc0 = 0.f, acc1 = 0.f, acc2 = 0.f, acc3 = 0.f;

#pragma unroll 1
    for (int ii = 0; ii < IN_DIM / 128; ++ii) {     // 8 iterations
        const int vec = ii * 32 + lane;             // float4 index in the row
        const float4 w4 = __ldg(wrow  + vec);
        const float4 a4 = __ldg(x0row + vec);
        const float4 b4 = __ldg(x1row + vec);
        const float4 c4 = __ldg(x2row + vec);
        const float4 d4 = __ldg(x3row + vec);
        const uint32_t cb = bk0 + (uint32_t)vec * 4u;
#pragma unroll
        for (int j = 0; j < 4; ++j) {
            const float wv = (&w4.x)[j];
            const uint32_t ci = cb + (uint32_t)j;

            const float t0 = __fmul_rn(wv, (&a4.x)[j]);
            const float t1 = __fmul_rn(wv, (&b4.x)[j]);
            const float t2 = __fmul_rn(wv, (&c4.x)[j]);
            const float t3 = __fmul_rn(wv, (&d4.x)[j]);

            const float m0 = bits_to_m(tf2x32_bits(ks1, ks2, ci));
            const float m1 = bits_to_m(tf2x32_bits(ks1, ks2, ci + RS));
            const float m2 = bits_to_m(tf2x32_bits(ks1, ks2, ci + 2u * RS));
            const float m3 = bits_to_m(tf2x32_bits(ks1, ks2, ci + 3u * RS));

            acc0 = __fmaf_rn(m0, t0, acc0);
            acc1 = __fmaf_rn(m1, t1, acc1);
            acc2 = __fmaf_rn(m2, t2, acc2);
            acc3 = __fmaf_rn(m3, t3, acc3);
        }
    }

    // warp butterfly reduce (4 accumulators)
#pragma unroll
    for (int off = 16; off > 0; off >>= 1) {
        acc0 += __shfl_xor_sync(0xFFFFFFFFu, acc0, off);
        acc1 += __shfl_xor_sync(0xFFFFFFFFu, acc1, off);
        acc2 += __shfl_xor_sync(0xFFFFFFFFu, acc2, off);
        acc3 += __shfl_xor_sync(0xFFFFFFFFu, acc3, off);
    }

    if (lane == 0) {
        const float bz = __ldg(bias + o);
        out[(size_t)(bp     ) * OUT_DIM + o] = acc0 + bz;
        out[(size_t)(bp + 16) * OUT_DIM + o] = acc1 + bz;
        out[(size_t)(bp + 32) * OUT_DIM + o] = acc2 + bz;
        out[(size_t)(bp + 48) * OUT_DIM + o] = acc3 + bz;
    }
}

extern "C" void kernel_launch(void* const* d_in, const int* in_sizes, int n_in,
                              void* d_out, int out_size) {
    const float* x    = (const float*)d_in[0];
    const float* w    = (const float*)d_in[1];
    const float* bias = (const float*)d_in[2];
    const int*   seed = (const int*)d_in[3];
    float* out = (float*)d_out;

    // 16 b-quads * 4096 outputs = 65536 warps; 8 warps/block -> 8192 blocks
    noise_linear_kernel<<<8192, 256>>>(x, w, bias, seed, out);
}

// round 7
// speedup vs baseline: 1.0797x; 1.0404x over previous
#include <cuda_runtime.h>
#include <cstdint>

// NoiseLinear: out[b,o] = sum_i x[b,i]*w[o,i]*(1 + 0.1*eps[b,o,i]) + bias[o]
// eps = jax.random.normal(key(seed), (B,OUT,IN)) — partitionable threefry
// (bit-model verified, rel_err ~2.6e-6).
// R7 = R6 (4 rows/warp, 16 chains/body) + packed f32x2 Giles polynomial:
// two elements share one FFMA2 Horner chain (PTX fma.rn.f32x2 — ptxas never
// emits FFMA2 from C++). Coefficient pairs hoisted into 64-bit regs.

#define B_DIM  64
#define IN_DIM 1024
#define OUT_DIM 4096

// ---- packed f32x2 helpers ----
#define PACK2(out, lo, hi) \
    asm("mov.b64 %0, {%1, %2};" : "=l"(out) : "f"(lo), "f"(hi))
#define UNPACK2(lo, hi, in) \
    asm("mov.b64 {%0, %1}, %2;" : "=f"(lo), "=f"(hi) : "l"(in))
#define FMA2(d, a, b, c) \
    asm("fma.rn.f32x2 %0, %1, %2, %3;" : "=l"(d) : "l"(a), "l"(b), "l"(c))

__device__ __forceinline__ uint64_t bcast2(float c) {
    uint32_t b = __float_as_uint(c);
    return ((uint64_t)b << 32) | (uint64_t)b;   // compile-time foldable
}

// Full 20-round threefry2x32, key (0, seed); returns o0 ^ o1.
// c1k = counter + ks1 (ks1 pre-folded by caller).
__device__ __forceinline__ uint32_t tf2x32_bits(uint32_t ks1, uint32_t ks2,
                                                uint32_t c1k) {
    uint32_t x0, x1 = c1k;
    x0 = x1;                                    // round 1 add (x0_init = 0)
    x1 = __funnelshift_l(x1, x1, 13); x1 ^= x0;
#define TF_R(r) { x0 += x1; x1 = __funnelshift_l(x1, x1, (r)); x1 ^= x0; }
    TF_R(15) TF_R(26) TF_R(6)
    x0 += ks1;      x1 += ks2 + 1u;
    TF_R(17) TF_R(29) TF_R(16) TF_R(24)
    x0 += ks2;      x1 += 2u;                   // + ks0(=0) + 2
    TF_R(13) TF_R(15) TF_R(26) TF_R(6)
    /* x0 += ks0 */ x1 += ks1 + 3u;
    TF_R(17) TF_R(29) TF_R(16) TF_R(24)
    x0 += ks1;      x1 += ks2 + 4u;
    TF_R(13) TF_R(15) TF_R(26) TF_R(6)
    x0 += ks2;      x1 += 5u;                   // + ks0(=0) + 5
#undef TF_R
    return x0 ^ x1;
}

// Scalar prelude: bits -> (u, s, L).  s = log2(1-u^2) + 2.5/ln2.
__device__ __forceinline__ void prelude(uint32_t bits, float& u, float& s,
                                        float& L) {
    float v = __uint_as_float((bits >> 9) + 0x3f800000u);   // [1,2)
    u = __fmaf_rn(v, 2.0f, -3.0f);                          // ~[-1,1)
    u = fmaxf(u, -0.99999994f);                             // keep 1-u^2 > 0
    float t = __fmaf_rn(u, -u, 1.0f);                       // (0,1]
    L = __log2f(t);
    s = __fadd_rn(L, 3.6067376f);
}

// Rare-tail polynomial (0.1*sqrt(2) folded), |u| >= 0.99663.
__device__ __forceinline__ float tail_poly(float L) {
    float w  = __fmul_rn(L, -0.69314718f);
    float wq = __fsqrt_rn(w) - 3.0f;
    float q;
    q = -2.8314768e-05f;
    q = __fmaf_rn(q, wq, 1.4276563e-05f);
    q = __fmaf_rn(q, wq, 1.9082642e-04f);
    q = __fmaf_rn(q, wq, -5.1950162e-04f);
    q = __fmaf_rn(q, wq, 8.1168864e-04f);
    q = __fmaf_rn(q, wq, -1.0779783e-03f);
    q = __fmaf_rn(q, wq, 1.3348632e-03f);
    q = __fmaf_rn(q, wq, 1.4165810e-01f);
    q = __fmaf_rn(q, wq, 4.0064343e-01f);
    return q;
}

// One warp per (b-quad, o). b-quad = bp, bp+16, bp+32, bp+48; bp in [0,16).
__global__ void __launch_bounds__(256, 3)
noise_linear_kernel(const float* __restrict__ x, const float* __restrict__ w,
                    const float* __restrict__ bias, const int* __restrict__ seedp,
                    float* __restrict__ out) {
    const uint32_t ks1 = (uint32_t)seedp[0];
    const uint32_t ks2 = ks1 ^ 0x1BD11BDAu;

    // packed central-poly coefficients (0.1*sqrt(2) folded; s-domain)
    const uint64_t C8 = bcast2(2.1176117e-10f);
    const uint64_t C7 = bcast2(-3.7320261e-09f);
    const uint64_t C6 = bcast2(-5.5262276e-08f);
    const uint64_t C5 = bcast2(9.9370005e-08f);
    const uint64_t C4 = bcast2(7.1355326e-06f);
    const uint64_t C3 = bcast2(5.9044926e-05f);
    const uint64_t C2 = bcast2(-2.8386012e-04f);
    const uint64_t C1 = bcast2(-2.4177344e-02f);
    const uint64_t C0 = bcast2(2.1233136e-01f);

    const int gw   = blockIdx.x * (blockDim.x >> 5) + (threadIdx.x >> 5);
    const int lane = threadIdx.x & 31;
    const int o  = gw & (OUT_DIM - 1);
    const int bp = gw >> 12;                 // 0..15

    const float4* __restrict__ wrow  = (const float4*)(w + (size_t)o * IN_DIM);
    const float4* __restrict__ x0row = (const float4*)(x + (size_t)(bp     ) * IN_DIM);
    const float4* __restrict__ x1row = (const float4*)(x + (size_t)(bp + 16) * IN_DIM);
    const float4* __restrict__ x2row = (const float4*)(x + (size_t)(bp + 32) * IN_DIM);
    const float4* __restrict__ x3row = (const float4*)(x + (size_t)(bp + 48) * IN_DIM);

    const uint32_t bk0 = (uint32_t)bp * (OUT_DIM * IN_DIM)
                       + (uint32_t)o * IN_DIM + ks1;
    const uint32_t RS = 16u * OUT_DIM * IN_DIM;

    float acc0 = 0.f, acc1 = 0.f, acc2 = 0.f, acc3 = 0.f;

#pragma unroll 1
    for (int ii = 0; ii < IN_DIM / 128; ++ii) {     // 8 iterations
        const int vec = ii * 32 + lane;
        const float4 w4 = __ldg(wrow  + vec);
        const float4 a4 = __ldg(x0row + vec);
        const float4 b4 = __ldg(x1row + vec);
        const float4 c4 = __ldg(x2row + vec);
        const float4 d4 = __ldg(x3row + vec);
        const uint32_t cb = bk0 + (uint32_t)vec * 4u;
#pragma unroll
        for (int j = 0; j < 4; ++j) {
            const float wv = (&w4.x)[j];
            const uint32_t ci = cb + (uint32_t)j;

            const float t0 = __fmul_rn(wv, (&a4.x)[j]);
            const float t1 = __fmul_rn(wv, (&b4.x)[j]);
            const float t2 = __fmul_rn(wv, (&c4.x)[j]);
            const float t3 = __fmul_rn(wv, (&d4.x)[j]);

            const uint32_t bits0 = tf2x32_bits(ks1, ks2, ci);
            const uint32_t bits1 = tf2x32_bits(ks1, ks2, ci + RS);
            const uint32_t bits2 = tf2x32_bits(ks1, ks2, ci + 2u * RS);
            const uint32_t bits3 = tf2x32_bits(ks1, ks2, ci + 3u * RS);

            float u0, s0, L0, u1, s1, L1, u2, s2, L2, u3, s3, L3;
            prelude(bits0, u0, s0, L0);
            prelude(bits1, u1, s1, L1);
            prelude(bits2, u2, s2, L2);
            prelude(bits3, u3, s3, L3);

            // packed Horner: pair A = (elem0, elem1), pair B = (elem2, elem3)
            uint64_t sA, sB, pA, pB;
            PACK2(sA, s0, s1);
            PACK2(sB, s2, s3);
            FMA2(pA, C8, sA, C7);   FMA2(pB, C8, sB, C7);
            FMA2(pA, pA, sA, C6);   FMA2(pB, pB, sB, C6);
            FMA2(pA, pA, sA, C5);   FMA2(pB, pB, sB, C5);
            FMA2(pA, pA, sA, C4);   FMA2(pB, pB, sB, C4);
            FMA2(pA, pA, sA, C3);   FMA2(pB, pB, sB, C3);
            FMA2(pA, pA, sA, C2);   FMA2(pB, pB, sB, C2);
            FMA2(pA, pA, sA, C1);   FMA2(pB, pB, sB, C1);
            FMA2(pA, pA, sA, C0);   FMA2(pB, pB, sB, C0);
            float p0, p1, p2, p3;
            UNPACK2(p0, p1, pA);
            UNPACK2(p2, p3, pB);

            // rare tail (|u| >= 0.99663; per-lane p=0.34%, warp-any ~10%)
            if (__any_sync(0xFFFFFFFFu, L0 <= -7.2134752f))
                p0 = (L0 <= -7.2134752f) ? tail_poly(L0) : p0;
            if (__any_sync(0xFFFFFFFFu, L1 <= -7.2134752f))
                p1 = (L1 <= -7.2134752f) ? tail_poly(L1) : p1;
            if (__any_sync(0xFFFFFFFFu, L2 <= -7.2134752f))
                p2 = (L2 <= -7.2134752f) ? tail_poly(L2) : p2;
            if (__any_sync(0xFFFFFFFFu, L3 <= -7.2134752f))
                p3 = (L3 <= -7.2134752f) ? tail_poly(L3) : p3;

            acc0 = __fmaf_rn(__fmaf_rn(p0, u0, 1.0f), t0, acc0);
            acc1 = __fmaf_rn(__fmaf_rn(p1, u1, 1.0f), t1, acc1);
            acc2 = __fmaf_rn(__fmaf_rn(p2, u2, 1.0f), t2, acc2);
            acc3 = __fmaf_rn(__fmaf_rn(p3, u3, 1.0f), t3, acc3);
        }
    }

    // warp butterfly reduce (4 accumulators)
#pragma unroll
    for (int off = 16; off > 0; off >>= 1) {
        acc0 += __shfl_xor_sync(0xFFFFFFFFu, acc0, off);
        acc1 += __shfl_xor_sync(0xFFFFFFFFu, acc1, off);
        acc2 += __shfl_xor_sync(0xFFFFFFFFu, acc2, off);
        acc3 += __shfl_xor_sync(0xFFFFFFFFu, acc3, off);
    }

    if (lane == 0) {
        const float bz = __ldg(bias + o);
        out[(size_t)(bp     ) * OUT_DIM + o] = acc0 + bz;
        out[(size_t)(bp + 16) * OUT_DIM + o] = acc1 + bz;
        out[(size_t)(bp + 32) * OUT_DIM + o] = acc2 + bz;
        out[(size_t)(bp + 48) * OUT_DIM + o] = acc3 + bz;
    }
}

extern "C" void kernel_launch(void* const* d_in, const int* in_sizes, int n_in,
                              void* d_out, int out_size) {
    const float* x    = (const float*)d_in[0];
    const float* w    = (const float*)d_in[1];
    const float* bias = (const float*)d_in[2];
    const int*   seed = (const int*)d_in[3];
    float* out = (float*)d_out;

    // 16 b-quads * 4096 outputs = 65536 warps; 8 warps/block -> 8192 blocks
    noise_linear_kernel<<<8192, 256>>>(x, w, bias, seed, out);
}

// round 8
// speedup vs baseline: 1.1030x; 1.0216x over previous
#include <cuda_runtime.h>
#include <cstdint>

// NoiseLinear: out[b,o] = sum_i x[b,i]*w[o,i]*(1 + 0.1*eps[b,o,i]) + bias[o]
// eps = jax.random.normal(key(seed), (B,OUT,IN)) — partitionable threefry
// (bit-model verified; R7 rel_err 2.63e-6).
// R8 = R7 + (a) cheap first-order-asymptotic tail (6 instr vs 12; abs err
// <2e-3 on 0.34% of samples — negligible vs 1e-3 output tolerance) and
// (b) packed L->s add via add.rn.f32x2 (saves 2 FADD per 4 elements).

#define B_DIM  64
#define IN_DIM 1024
#define OUT_DIM 4096

// ---- packed f32x2 helpers ----
#define PACK2(out, lo, hi) \
    asm("mov.b64 %0, {%1, %2};" : "=l"(out) : "f"(lo), "f"(hi))
#define UNPACK2(lo, hi, in) \
    asm("mov.b64 {%0, %1}, %2;" : "=f"(lo), "=f"(hi) : "l"(in))
#define FMA2(d, a, b, c) \
    asm("fma.rn.f32x2 %0, %1, %2, %3;" : "=l"(d) : "l"(a), "l"(b), "l"(c))
#define ADD2(d, a, b) \
    asm("add.rn.f32x2 %0, %1, %2;" : "=l"(d) : "l"(a), "l"(b))

__device__ __forceinline__ uint64_t bcast2(float c) {
    uint32_t b = __float_as_uint(c);
    return ((uint64_t)b << 32) | (uint64_t)b;   // compile-time foldable
}

// Full 20-round threefry2x32, key (0, seed); returns o0 ^ o1.
// c1k = counter + ks1 (ks1 pre-folded by caller).
__device__ __forceinline__ uint32_t tf2x32_bits(uint32_t ks1, uint32_t ks2,
                                                uint32_t c1k) {
    uint32_t x0, x1 = c1k;
    x0 = x1;                                    // round 1 add (x0_init = 0)
    x1 = __funnelshift_l(x1, x1, 13); x1 ^= x0;
#define TF_R(r) { x0 += x1; x1 = __funnelshift_l(x1, x1, (r)); x1 ^= x0; }
    TF_R(15) TF_R(26) TF_R(6)
    x0 += ks1;      x1 += ks2 + 1u;
    TF_R(17) TF_R(29) TF_R(16) TF_R(24)
    x0 += ks2;      x1 += 2u;                   // + ks0(=0) + 2
    TF_R(13) TF_R(15) TF_R(26) TF_R(6)
    /* x0 += ks0 */ x1 += ks1 + 3u;
    TF_R(17) TF_R(29) TF_R(16) TF_R(24)
    x0 += ks1;      x1 += ks2 + 4u;
    TF_R(13) TF_R(15) TF_R(26) TF_R(6)
    x0 += ks2;      x1 += 5u;                   // + ks0(=0) + 5
#undef TF_R
    return x0 ^ x1;
}

// Scalar prelude: bits -> (u, L).  L = log2(1-u^2).
__device__ __forceinline__ void prelude(uint32_t bits, float& u, float& L) {
    float v = __uint_as_float((bits >> 9) + 0x3f800000u);   // [1,2)
    u = __fmaf_rn(v, 2.0f, -3.0f);                          // ~[-1,1)
    u = fmaxf(u, -0.99999994f);                             // keep 1-u^2 > 0
    float t = __fmaf_rn(u, -u, 1.0f);                       // (0,1]
    L = __log2f(t);
}

// Cheap rare-tail (w = -ln(1-u^2) >= 5, i.e. |u| >= 0.99663):
// first-order erfc asymptotic y^2 = w - 0.5*ln(w) + (ln2 - 0.5*ln(pi)),
// q = 0.1*sqrt(2)*y (with mean 1/|u| correction folded: x1.0017).
// Abs err < ~2e-3 on 0.34% of samples -> ~1e-5 output rel_err.
__device__ __forceinline__ float cheap_tail(float L) {
    float w  = __fmul_rn(L, -0.69314718f);          // w > 5
    float t1 = __fadd_rn(w, 0.12078223f);           // w + ln2 - 0.5*ln(pi)
    float g  = __log2f(w);
    float y2 = __fmaf_rn(g, -0.34657359f, t1);      // w - 0.5*ln(w) + c0
    float y  = __fsqrt_rn(y2);
    return __fmul_rn(y, 0.14166f);                  // 0.1*sqrt(2)*1.0017
}

// One warp per (b-quad, o). b-quad = bp, bp+16, bp+32, bp+48; bp in [0,16).
__global__ void __launch_bounds__(256, 3)
noise_linear_kernel(const float* __restrict__ x, const float* __restrict__ w,
                    const float* __restrict__ bias, const int* __restrict__ seedp,
                    float* __restrict__ out) {
    const uint32_t ks1 = (uint32_t)seedp[0];
    const uint32_t ks2 = ks1 ^ 0x1BD11BDAu;

    // packed central-poly coefficients (0.1*sqrt(2) folded; s-domain,
    // s = log2(1-u^2) + 2.5/ln2)
    const uint64_t C8 = bcast2(2.1176117e-10f);
    const uint64_t C7 = bcast2(-3.7320261e-09f);
    const uint64_t C6 = bcast2(-5.5262276e-08f);
    const uint64_t C5 = bcast2(9.9370005e-08f);
    const uint64_t C4 = bcast2(7.1355326e-06f);
    const uint64_t C3 = bcast2(5.9044926e-05f);
    const uint64_t C2 = bcast2(-2.8386012e-04f);
    const uint64_t C1 = bcast2(-2.4177344e-02f);
    const uint64_t C0 = bcast2(2.1233136e-01f);
    const uint64_t SK = bcast2(3.6067376f);          // +2.5/ln2 (packed)

    const int gw   = blockIdx.x * (blockDim.x >> 5) + (threadIdx.x >> 5);
    const int lane = threadIdx.x & 31;
    const int o  = gw & (OUT_DIM - 1);
    const int bp = gw >> 12;                 // 0..15

    const float4* __restrict__ wrow  = (const float4*)(w + (size_t)o * IN_DIM);
    const float4* __restrict__ x0row = (const float4*)(x + (size_t)(bp     ) * IN_DIM);
    const float4* __restrict__ x1row = (const float4*)(x + (size_t)(bp + 16) * IN_DIM);
    const float4* __restrict__ x2row = (const float4*)(x + (size_t)(bp + 32) * IN_DIM);
    const float4* __restrict__ x3row = (const float4*)(x + (size_t)(bp + 48) * IN_DIM);

    const uint32_t bk0 = (uint32_t)bp * (OUT_DIM * IN_DIM)
                       + (uint32_t)o * IN_DIM + ks1;
    const uint32_t RS = 16u * OUT_DIM * IN_DIM;

    float acc0 = 0.f, acc1 = 0.f, acc2 = 0.f, acc3 = 0.f;

#pragma unroll 1
    for (int ii = 0; ii < IN_DIM / 128; ++ii) {     // 8 iterations
        const int vec = ii * 32 + lane;
        const float4 w4 = __ldg(wrow  + vec);
        const float4 a4 = __ldg(x0row + vec);
        const float4 b4 = __ldg(x1row + vec);
        const float4 c4 = __ldg(x2row + vec);
        const float4 d4 = __ldg(x3row + vec);
        const uint32_t cb = bk0 + (uint32_t)vec * 4u;
#pragma unroll
        for (int j = 0; j < 4; ++j) {
            const float wv = (&w4.x)[j];
            const uint32_t ci = cb + (uint32_t)j;

            const float t0 = __fmul_rn(wv, (&a4.x)[j]);
            const float t1 = __fmul_rn(wv, (&b4.x)[j]);
            const float t2 = __fmul_rn(wv, (&c4.x)[j]);
            const float t3 = __fmul_rn(wv, (&d4.x)[j]);

            const uint32_t bits0 = tf2x32_bits(ks1, ks2, ci);
            const uint32_t bits1 = tf2x32_bits(ks1, ks2, ci + RS);
            const uint32_t bits2 = tf2x32_bits(ks1, ks2, ci + 2u * RS);
            const uint32_t bits3 = tf2x32_bits(ks1, ks2, ci + 3u * RS);

            float u0, L0, u1, L1, u2, L2, u3, L3;
            prelude(bits0, u0, L0);
            prelude(bits1, u1, L1);
            prelude(bits2, u2, L2);
            prelude(bits3, u3, L3);

            // packed s = L + 2.5/ln2, then packed Horner
            uint64_t LA, LB, sA, sB, pA, pB;
            PACK2(LA, L0, L1);
            PACK2(LB, L2, L3);
            ADD2(sA, LA, SK);
            ADD2(sB, LB, SK);
            FMA2(pA, C8, sA, C7);   FMA2(pB, C8, sB, C7);
            FMA2(pA, pA, sA, C6);   FMA2(pB, pB, sB, C6);
            FMA2(pA, pA, sA, C5);   FMA2(pB, pB, sB, C5);
            FMA2(pA, pA, sA, C4);   FMA2(pB, pB, sB, C4);
            FMA2(pA, pA, sA, C3);   FMA2(pB, pB, sB, C3);
            FMA2(pA, pA, sA, C2);   FMA2(pB, pB, sB, C2);
            FMA2(pA, pA, sA, C1);   FMA2(pB, pB, sB, C1);
            FMA2(pA, pA, sA, C0);   FMA2(pB, pB, sB, C0);
            float p0, p1, p2, p3;
            UNPACK2(p0, p1, pA);
            UNPACK2(p2, p3, pB);

            // rare tail (|u| >= 0.99663; per-lane p=0.34%, warp-any ~10%)
            if (__any_sync(0xFFFFFFFFu, L0 <= -7.2134752f))
                p0 = (L0 <= -7.2134752f) ? cheap_tail(L0) : p0;
            if (__any_sync(0xFFFFFFFFu, L1 <= -7.2134752f))
                p1 = (L1 <= -7.2134752f) ? cheap_tail(L1) : p1;
            if (__any_sync(0xFFFFFFFFu, L2 <= -7.2134752f))
                p2 = (L2 <= -7.2134752f) ? cheap_tail(L2) : p2;
            if (__any_sync(0xFFFFFFFFu, L3 <= -7.2134752f))
                p3 = (L3 <= -7.2134752f) ? cheap_tail(L3) : p3;

            acc0 = __fmaf_rn(__fmaf_rn(p0, u0, 1.0f), t0, acc0);
            acc1 = __fmaf_rn(__fmaf_rn(p1, u1, 1.0f), t1, acc1);
            acc2 = __fmaf_rn(__fmaf_rn(p2, u2, 1.0f), t2, acc2);
            acc3 = __fmaf_rn(__fmaf_rn(p3, u3, 1.0f), t3, acc3);
        }
    }

    // warp butterfly reduce (4 accumulators)
#pragma unroll
    for (int off = 16; off > 0; off >>= 1) {
        acc0 += __shfl_xor_sync(0xFFFFFFFFu, acc0, off);
        acc1 += __shfl_xor_sync(0xFFFFFFFFu, acc1, off);
        acc2 += __shfl_xor_sync(0xFFFFFFFFu, acc2, off);
        acc3 += __shfl_xor_sync(0xFFFFFFFFu, acc3, off);
    }

    if (lane == 0) {
        const float bz = __ldg(bias + o);
        out[(size_t)(bp     ) * OUT_DIM + o] = acc0 + bz;
        out[(size_t)(bp + 16) * OUT_DIM + o] = acc1 + bz;
        out[(size_t)(bp + 32) * OUT_DIM + o] = acc2 + bz;
        out[(size_t)(bp + 48) * OUT_DIM + o] = acc3 + bz;
    }
}

extern "C" void kernel_launch(void* const* d_in, const int* in_sizes, int n_in,
                              void* d_out, int out_size) {
    const float* x    = (const float*)d_in[0];
    const float* w    = (const float*)d_in[1];
    const float* bias = (const float*)d_in[2];
    const int*   seed = (const int*)d_in[3];
    float* out = (float*)d_out;

    // 16 b-quads * 4096 outputs = 65536 warps; 8 warps/block -> 8192 blocks
    noise_linear_kernel<<<8192, 256>>>(x, w, bias, seed, out);
}